// round 3
// baseline (speedup 1.0000x reference)
#include <cuda_runtime.h>

// ACT-LSTM persistent kernel, v2.
// Key structure vs v1:
//  - Step-0 gates fused: one pass reads W_ih and W_hh together (max MLP).
//  - Phase B (activations + halt decision) computed REDUNDANTLY by every block
//    on block-local shared h/c (identical fp ops -> identical halt decision),
//    eliminating the serial block-0 phase and one grid barrier per step.
//  - g_gates double-buffered so only ONE grid barrier per step is needed.
//  - Epilogue is barrier-free (each block has final h in shared).
//
// I=1024, H=2048, O=1024, 4H=8192, MAX_STEPS=20.

#define NBLOCK 148
#define NTHREAD 512
#define WPB (NTHREAD / 32)            // 16 warps/block
#define TOTAL_WARPS (NBLOCK * WPB)    // 2368
#define HDIM 2048
#define IDIM 1024
#define ODIM 1024
#define G4 (4 * HDIM)                 // 8192
#define MAX_STEPS 20

// -------- device scratch (no allocation allowed) --------
__device__ float g_gates[2][G4];      // double-buffered gate pre-activations

// -------- manual grid barrier --------
__device__ unsigned g_bar_count = 0;
__device__ volatile unsigned g_bar_gen = 0;

__device__ __forceinline__ void grid_sync() {
    __syncthreads();
    if (threadIdx.x == 0) {
        __threadfence();                       // release prior global writes
        unsigned gen = g_bar_gen;
        if (atomicAdd(&g_bar_count, 1u) == NBLOCK - 1) {
            g_bar_count = 0u;
            __threadfence();
            g_bar_gen = gen + 1u;
        } else {
            while (g_bar_gen == gen) { __nanosleep(32); }
            __threadfence();                   // acquire
        }
    }
    __syncthreads();
}

__device__ __forceinline__ float warp_reduce(float v) {
    #pragma unroll
    for (int off = 16; off; off >>= 1) v += __shfl_xor_sync(0xffffffffu, v, off);
    return v;
}

__device__ __forceinline__ float sigmoidf_(float x) {
    return 1.0f / (1.0f + __expf(-x));
}

__global__ __launch_bounds__(NTHREAD, 1)
void act_lstm_kernel(const float* __restrict__ x,
                     const float* __restrict__ h0,
                     const float* __restrict__ c0,
                     const float* __restrict__ W_ih,
                     const float* __restrict__ W_hh,
                     const float* __restrict__ b_ih,
                     const float* __restrict__ b_hh,
                     const float* __restrict__ w_halt,
                     const float* __restrict__ b_halt,
                     const float* __restrict__ W_out,
                     const float* __restrict__ b_out,
                     float* __restrict__ gx,      // scratch via out tail? no: device global below
                     float* __restrict__ out) {
    // block-local replicated state
    __shared__ float sh_h[HDIM];
    __shared__ float sh_c[HDIM];
    __shared__ float sh_x[IDIM];
    __shared__ float s_red[WPB];

    const int tid   = threadIdx.x;
    const int lane  = tid & 31;
    const int warp  = tid >> 5;
    const int gwarp = blockIdx.x * WPB + warp;

    // ---- init local state ----
    for (int j = tid; j < HDIM; j += NTHREAD) {
        sh_h[j] = h0[j];
        sh_c[j] = c0[j];
    }
    for (int j = tid; j < IDIM; j += NTHREAD) sh_x[j] = x[j];
    const float bh = b_halt[0];
    __syncthreads();

    // ---- fused phase: gates(t=0) = W_ih@[1,x] + b_ih + b_hh + W_hh@h0 ----
    // also stores gx[r] = W_ih[r,1:]@x + b_ih + b_hh for later steps.
    for (int r = gwarp; r < G4; r += TOTAL_WARPS) {
        const float*  wi = W_ih + (size_t)r * (IDIM + 1);
        const float4* wh = (const float4*)(W_hh + (size_t)r * HDIM);
        const float4* hv = (const float4*)sh_h;
        float a_ih = 0.0f;
        #pragma unroll 8
        for (int k = lane; k < IDIM; k += 32) a_ih += __ldg(wi + 1 + k) * sh_x[k];
        float a_hh = 0.0f;
        #pragma unroll 16
        for (int k = lane; k < HDIM / 4; k += 32) {
            float4 w = __ldg(wh + k);
            float4 h4 = hv[k];
            a_hh += w.x * h4.x + w.y * h4.y + w.z * h4.z + w.w * h4.w;
        }
        a_ih = warp_reduce(a_ih);
        a_hh = warp_reduce(a_hh);
        if (lane == 0) {
            float base = a_ih + b_ih[r] + b_hh[r];
            gx[r] = base;
            g_gates[0][r] = base + wi[0] + a_hh;   // flag column active at t=0
        }
    }
    grid_sync();

    // ---- adaptive loop: ONE grid barrier per step ----
    float cum = 0.0f;
    int   halted_t = MAX_STEPS - 1;
    int   buf = 0;

    for (int t = 0; t < MAX_STEPS; ++t) {
        // phase B (every block, redundant, block-local): activations + halt
        const float* gt = g_gates[buf];
        float part = 0.0f;
        for (int j = tid; j < HDIM; j += NTHREAD) {
            float gi = gt[j];
            float gf = gt[HDIM + j];
            float gg = gt[2 * HDIM + j];
            float go = gt[3 * HDIM + j];
            float cn = sigmoidf_(gf) * sh_c[j] + sigmoidf_(gi) * tanhf(gg);
            float hn = sigmoidf_(go) * tanhf(cn);
            sh_c[j] = cn;
            sh_h[j] = hn;
            part += w_halt[j] * hn;
        }
        part = warp_reduce(part);
        if (lane == 0) s_red[warp] = part;
        __syncthreads();
        float dot = 0.0f;
        #pragma unroll
        for (int w2 = 0; w2 < WPB; ++w2) dot += s_red[w2];
        float p = sigmoidf_(dot + bh);
        cum += p;
        if (cum >= 0.99f || t == MAX_STEPS - 1) { halted_t = t; break; }

        // phase A for step t+1: gates = gx + W_hh @ h   (h is block-local shared)
        buf ^= 1;
        float* gn = g_gates[buf];
        for (int r = gwarp; r < G4; r += TOTAL_WARPS) {
            const float4* wh = (const float4*)(W_hh + (size_t)r * HDIM);
            const float4* hv = (const float4*)sh_h;
            float acc = 0.0f;
            #pragma unroll 16
            for (int k = lane; k < HDIM / 4; k += 32) {
                float4 w = __ldg(wh + k);
                float4 h4 = hv[k];
                acc += w.x * h4.x + w.y * h4.y + w.z * h4.z + w.w * h4.w;
            }
            acc = warp_reduce(acc);
            if (lane == 0) gn[r] = gx[r] + acc;
        }
        grid_sync();
        __syncthreads();   // ensure s_red reuse + sh_h stable (grid_sync has one, keep for clarity)
    }

    // ---- epilogue (barrier-free): out = W_out @ h + b_out; emit h, c, ponder ----
    __syncthreads();
    for (int r = gwarp; r < ODIM; r += TOTAL_WARPS) {
        const float4* wr = (const float4*)(W_out + (size_t)r * HDIM);
        const float4* hv = (const float4*)sh_h;
        float acc = 0.0f;
        #pragma unroll 16
        for (int k = lane; k < HDIM / 4; k += 32) {
            float4 w = __ldg(wr + k);
            float4 h4 = hv[k];
            acc += w.x * h4.x + w.y * h4.y + w.z * h4.z + w.w * h4.w;
        }
        acc = warp_reduce(acc);
        if (lane == 0) out[r] = acc + b_out[r];
    }

    if (blockIdx.x == 0) {
        for (int j = tid; j < HDIM; j += NTHREAD) {
            out[ODIM + j]        = sh_h[j];
            out[ODIM + HDIM + j] = sh_c[j];
        }
        if (tid == 0) out[ODIM + 2 * HDIM] = (float)halted_t;
    }
}

// gx scratch lives in device global (no allocation allowed)
__device__ float g_gx_buf[G4];

extern "C" void kernel_launch(void* const* d_in, const int* in_sizes, int n_in,
                              void* d_out, int out_size) {
    (void)in_sizes; (void)n_in; (void)out_size;
    const float* x      = (const float*)d_in[0];
    const float* h0     = (const float*)d_in[1];
    const float* c0     = (const float*)d_in[2];
    const float* W_ih   = (const float*)d_in[3];
    const float* W_hh   = (const float*)d_in[4];
    const float* b_ih   = (const float*)d_in[5];
    const float* b_hh   = (const float*)d_in[6];
    const float* w_halt = (const float*)d_in[7];
    const float* b_halt = (const float*)d_in[8];
    const float* W_out  = (const float*)d_in[9];
    const float* b_out  = (const float*)d_in[10];
    float* out = (float*)d_out;

    float* gx_ptr = nullptr;
    cudaGetSymbolAddress((void**)&gx_ptr, g_gx_buf);

    act_lstm_kernel<<<NBLOCK, NTHREAD>>>(x, h0, c0, W_ih, W_hh, b_ih, b_hh,
                                         w_halt, b_halt, W_out, b_out,
                                         gx_ptr, out);
}

// round 4
// speedup vs baseline: 1.0454x; 1.0454x over previous
#include <cuda_runtime.h>

// ACT-LSTM persistent kernel, v3.
// vs v2: 4 CONSECUTIVE rows per warp with 4 independent accumulator chains
// (breaks the serial FMA dependency, 4x ILP, 1/4 LDS traffic), reductions
// paid once per warp for the whole kernel, exact load balance
// (128 blocks x 16 warps x 4 rows = 8192 = 4H).
//
// I=1024, H=2048, O=1024, 4H=8192, MAX_STEPS=20.

#define NBLOCK 128
#define NTHREAD 512
#define WPB (NTHREAD / 32)            // 16 warps/block
#define NWARP (NBLOCK * WPB)          // 2048
#define HDIM 2048
#define IDIM 1024
#define ODIM 1024
#define G4 (4 * HDIM)                 // 8192
#define MAX_STEPS 20

// -------- device scratch (no allocation allowed) --------
__device__ float g_gates[2][G4];      // double-buffered gate pre-activations
__device__ float g_gx_buf[G4];        // W_ih[:,1:]@x + b_ih + b_hh (step-invariant)

// -------- manual grid barrier --------
__device__ unsigned g_bar_count = 0;
__device__ volatile unsigned g_bar_gen = 0;

__device__ __forceinline__ void grid_sync() {
    __syncthreads();
    if (threadIdx.x == 0) {
        __threadfence();
        unsigned gen = g_bar_gen;
        if (atomicAdd(&g_bar_count, 1u) == NBLOCK - 1) {
            g_bar_count = 0u;
            __threadfence();
            g_bar_gen = gen + 1u;
        } else {
            while (g_bar_gen == gen) { __nanosleep(32); }
            __threadfence();
        }
    }
    __syncthreads();
}

__device__ __forceinline__ float warp_reduce(float v) {
    #pragma unroll
    for (int off = 16; off; off >>= 1) v += __shfl_xor_sync(0xffffffffu, v, off);
    return v;
}

__device__ __forceinline__ float sigmoidf_(float x) {
    return 1.0f / (1.0f + __expf(-x));
}

__global__ __launch_bounds__(NTHREAD, 1)
void act_lstm_kernel(const float* __restrict__ x,
                     const float* __restrict__ h0,
                     const float* __restrict__ c0,
                     const float* __restrict__ W_ih,
                     const float* __restrict__ W_hh,
                     const float* __restrict__ b_ih,
                     const float* __restrict__ b_hh,
                     const float* __restrict__ w_halt,
                     const float* __restrict__ b_halt,
                     const float* __restrict__ W_out,
                     const float* __restrict__ b_out,
                     float* __restrict__ out) {
    __shared__ float sh_h[HDIM];
    __shared__ float sh_c[HDIM];
    __shared__ float sh_x[IDIM];
    __shared__ float s_red[WPB];

    const int tid   = threadIdx.x;
    const int lane  = tid & 31;
    const int warp  = tid >> 5;
    const int gwarp = blockIdx.x * WPB + warp;
    const int r0    = gwarp * 4;          // this warp's 4 gate rows

    // ---- init block-local state ----
    for (int j = tid; j < HDIM; j += NTHREAD) {
        sh_h[j] = h0[j];
        sh_c[j] = c0[j];
    }
    for (int j = tid; j < IDIM; j += NTHREAD) sh_x[j] = x[j];
    const float bh = b_halt[0];
    __syncthreads();

    // ---- fused phase: gates(t=0) = W_ih@[1,x] + b_ih + b_hh + W_hh@h0 ----
    {
        const float* wi = W_ih + (size_t)r0 * (IDIM + 1);
        float ai0 = 0.f, ai1 = 0.f, ai2 = 0.f, ai3 = 0.f;
        #pragma unroll 4
        for (int k = lane; k < IDIM; k += 32) {
            float xv = sh_x[k];
            ai0 += __ldg(wi + 1 + k) * xv;
            ai1 += __ldg(wi + (IDIM + 1) + 1 + k) * xv;
            ai2 += __ldg(wi + 2 * (IDIM + 1) + 1 + k) * xv;
            ai3 += __ldg(wi + 3 * (IDIM + 1) + 1 + k) * xv;
        }

        const float4* wh = (const float4*)(W_hh + (size_t)r0 * HDIM);
        const float4* hv = (const float4*)sh_h;
        float ah0 = 0.f, ah1 = 0.f, ah2 = 0.f, ah3 = 0.f;
        #pragma unroll 2
        for (int k = lane; k < HDIM / 4; k += 32) {
            float4 h4 = hv[k];
            float4 w0 = __ldg(wh + k);
            float4 w1 = __ldg(wh + (HDIM / 4) + k);
            float4 w2 = __ldg(wh + 2 * (HDIM / 4) + k);
            float4 w3 = __ldg(wh + 3 * (HDIM / 4) + k);
            ah0 += w0.x * h4.x + w0.y * h4.y + w0.z * h4.z + w0.w * h4.w;
            ah1 += w1.x * h4.x + w1.y * h4.y + w1.z * h4.z + w1.w * h4.w;
            ah2 += w2.x * h4.x + w2.y * h4.y + w2.z * h4.z + w2.w * h4.w;
            ah3 += w3.x * h4.x + w3.y * h4.y + w3.z * h4.z + w3.w * h4.w;
        }

        ai0 = warp_reduce(ai0); ai1 = warp_reduce(ai1);
        ai2 = warp_reduce(ai2); ai3 = warp_reduce(ai3);
        ah0 = warp_reduce(ah0); ah1 = warp_reduce(ah1);
        ah2 = warp_reduce(ah2); ah3 = warp_reduce(ah3);

        if (lane == 0) {
            float b0 = ai0 + b_ih[r0 + 0] + b_hh[r0 + 0];
            float b1 = ai1 + b_ih[r0 + 1] + b_hh[r0 + 1];
            float b2 = ai2 + b_ih[r0 + 2] + b_hh[r0 + 2];
            float b3 = ai3 + b_ih[r0 + 3] + b_hh[r0 + 3];
            g_gx_buf[r0 + 0] = b0;
            g_gx_buf[r0 + 1] = b1;
            g_gx_buf[r0 + 2] = b2;
            g_gx_buf[r0 + 3] = b3;
            g_gates[0][r0 + 0] = b0 + wi[0]                + ah0;
            g_gates[0][r0 + 1] = b1 + wi[IDIM + 1]         + ah1;
            g_gates[0][r0 + 2] = b2 + wi[2 * (IDIM + 1)]   + ah2;
            g_gates[0][r0 + 3] = b3 + wi[3 * (IDIM + 1)]   + ah3;
        }
    }
    grid_sync();

    // ---- adaptive loop: ONE grid barrier per step ----
    float cum = 0.0f;
    int   halted_t = MAX_STEPS - 1;
    int   buf = 0;

    for (int t = 0; t < MAX_STEPS; ++t) {
        // phase B: activations + halt (redundant per block, block-local state)
        const float* gt = g_gates[buf];
        float part = 0.0f;
        for (int j = tid; j < HDIM; j += NTHREAD) {
            float gi = gt[j];
            float gf = gt[HDIM + j];
            float gg = gt[2 * HDIM + j];
            float go = gt[3 * HDIM + j];
            float cn = sigmoidf_(gf) * sh_c[j] + sigmoidf_(gi) * tanhf(gg);
            float hn = sigmoidf_(go) * tanhf(cn);
            sh_c[j] = cn;
            sh_h[j] = hn;
            part += w_halt[j] * hn;
        }
        part = warp_reduce(part);
        if (lane == 0) s_red[warp] = part;
        __syncthreads();
        float dot = 0.0f;
        #pragma unroll
        for (int w2 = 0; w2 < WPB; ++w2) dot += s_red[w2];
        float p = sigmoidf_(dot + bh);
        cum += p;
        if (cum >= 0.99f || t == MAX_STEPS - 1) { halted_t = t; break; }

        // phase A for step t+1: gates = gx + W_hh @ h (4 rows/warp, 4 chains)
        buf ^= 1;
        float* gn = g_gates[buf];
        {
            const float4* wh = (const float4*)(W_hh + (size_t)r0 * HDIM);
            const float4* hv = (const float4*)sh_h;
            float ah0 = 0.f, ah1 = 0.f, ah2 = 0.f, ah3 = 0.f;
            #pragma unroll 2
            for (int k = lane; k < HDIM / 4; k += 32) {
                float4 h4 = hv[k];
                float4 w0 = __ldg(wh + k);
                float4 w1 = __ldg(wh + (HDIM / 4) + k);
                float4 w2 = __ldg(wh + 2 * (HDIM / 4) + k);
                float4 w3 = __ldg(wh + 3 * (HDIM / 4) + k);
                ah0 += w0.x * h4.x + w0.y * h4.y + w0.z * h4.z + w0.w * h4.w;
                ah1 += w1.x * h4.x + w1.y * h4.y + w1.z * h4.z + w1.w * h4.w;
                ah2 += w2.x * h4.x + w2.y * h4.y + w2.z * h4.z + w2.w * h4.w;
                ah3 += w3.x * h4.x + w3.y * h4.y + w3.z * h4.z + w3.w * h4.w;
            }
            ah0 = warp_reduce(ah0); ah1 = warp_reduce(ah1);
            ah2 = warp_reduce(ah2); ah3 = warp_reduce(ah3);
            if (lane == 0) {
                gn[r0 + 0] = g_gx_buf[r0 + 0] + ah0;
                gn[r0 + 1] = g_gx_buf[r0 + 1] + ah1;
                gn[r0 + 2] = g_gx_buf[r0 + 2] + ah2;
                gn[r0 + 3] = g_gx_buf[r0 + 3] + ah3;
            }
        }
        grid_sync();
    }

    // ---- epilogue (barrier-free): out = W_out @ h + b_out; emit h, c, ponder --
    __syncthreads();
    if (gwarp < ODIM) {
        const int r = gwarp;
        const float4* wr = (const float4*)(W_out + (size_t)r * HDIM);
        const float4* hv = (const float4*)sh_h;
        float a0 = 0.f, a1 = 0.f;
        #pragma unroll 4
        for (int k = lane; k < HDIM / 4; k += 64) {
            float4 w = __ldg(wr + k);
            float4 h4 = hv[k];
            a0 += w.x * h4.x + w.y * h4.y + w.z * h4.z + w.w * h4.w;
            float4 w2 = __ldg(wr + k + 32);
            float4 h42 = hv[k + 32];
            a1 += w2.x * h42.x + w2.y * h42.y + w2.z * h42.z + w2.w * h42.w;
        }
        float acc = warp_reduce(a0 + a1);
        if (lane == 0) out[r] = acc + b_out[r];
    }

    if (blockIdx.x == 0) {
        for (int j = tid; j < HDIM; j += NTHREAD) {
            out[ODIM + j]        = sh_h[j];
            out[ODIM + HDIM + j] = sh_c[j];
        }
        if (tid == 0) out[ODIM + 2 * HDIM] = (float)halted_t;
    }
}

extern "C" void kernel_launch(void* const* d_in, const int* in_sizes, int n_in,
                              void* d_out, int out_size) {
    (void)in_sizes; (void)n_in; (void)out_size;
    const float* x      = (const float*)d_in[0];
    const float* h0     = (const float*)d_in[1];
    const float* c0     = (const float*)d_in[2];
    const float* W_ih   = (const float*)d_in[3];
    const float* W_hh   = (const float*)d_in[4];
    const float* b_ih   = (const float*)d_in[5];
    const float* b_hh   = (const float*)d_in[6];
    const float* w_halt = (const float*)d_in[7];
    const float* b_halt = (const float*)d_in[8];
    const float* W_out  = (const float*)d_in[9];
    const float* b_out  = (const float*)d_in[10];
    float* out = (float*)d_out;

    act_lstm_kernel<<<NBLOCK, NTHREAD>>>(x, h0, c0, W_ih, W_hh, b_ih, b_hh,
                                         w_halt, b_halt, W_out, b_out, out);
}

// round 5
// speedup vs baseline: 1.3872x; 1.3270x over previous
#include <cuda_runtime.h>

// ACT-LSTM persistent kernel, v4.
// vs v3: occupancy 25% -> 50% (1024-thread blocks, 32 warps/SM) to double
// per-SM memory-level parallelism; 2 rows/warp (128 blk x 32 w x 2 = 8192);
// epilogue splits each W_out row across 4 warps (all blocks active).
//
// I=1024, H=2048, O=1024, 4H=8192, MAX_STEPS=20.

#define NBLOCK 128
#define NTHREAD 1024
#define WPB (NTHREAD / 32)            // 32 warps/block
#define NWARP (NBLOCK * WPB)          // 4096
#define HDIM 2048
#define IDIM 1024
#define ODIM 1024
#define G4 (4 * HDIM)                 // 8192
#define MAX_STEPS 20

// -------- device scratch (no allocation allowed) --------
__device__ float g_gates[2][G4];      // double-buffered gate pre-activations
__device__ float g_gx_buf[G4];        // W_ih[:,1:]@x + b_ih + b_hh (step-invariant)

// -------- manual grid barrier --------
__device__ unsigned g_bar_count = 0;
__device__ volatile unsigned g_bar_gen = 0;

__device__ __forceinline__ void grid_sync() {
    __syncthreads();
    if (threadIdx.x == 0) {
        __threadfence();
        unsigned gen = g_bar_gen;
        if (atomicAdd(&g_bar_count, 1u) == NBLOCK - 1) {
            g_bar_count = 0u;
            __threadfence();
            g_bar_gen = gen + 1u;
        } else {
            while (g_bar_gen == gen) { __nanosleep(32); }
            __threadfence();
        }
    }
    __syncthreads();
}

__device__ __forceinline__ float warp_reduce(float v) {
    #pragma unroll
    for (int off = 16; off; off >>= 1) v += __shfl_xor_sync(0xffffffffu, v, off);
    return v;
}

__device__ __forceinline__ float sigmoidf_(float x) {
    return 1.0f / (1.0f + __expf(-x));
}

__global__ __launch_bounds__(NTHREAD, 1)
void act_lstm_kernel(const float* __restrict__ x,
                     const float* __restrict__ h0,
                     const float* __restrict__ c0,
                     const float* __restrict__ W_ih,
                     const float* __restrict__ W_hh,
                     const float* __restrict__ b_ih,
                     const float* __restrict__ b_hh,
                     const float* __restrict__ w_halt,
                     const float* __restrict__ b_halt,
                     const float* __restrict__ W_out,
                     const float* __restrict__ b_out,
                     float* __restrict__ out) {
    __shared__ float sh_h[HDIM];
    __shared__ float sh_c[HDIM];
    __shared__ float sh_x[IDIM];
    __shared__ float s_red[WPB];

    const int tid   = threadIdx.x;
    const int lane  = tid & 31;
    const int warp  = tid >> 5;
    const int gwarp = blockIdx.x * WPB + warp;
    const int r0    = gwarp * 2;          // this warp's 2 gate rows

    // ---- init block-local state ----
    for (int j = tid; j < HDIM; j += NTHREAD) {
        sh_h[j] = h0[j];
        sh_c[j] = c0[j];
    }
    if (tid < IDIM) sh_x[tid] = x[tid];
    const float bh = b_halt[0];
    __syncthreads();

    // ---- fused phase: gates(t=0) = W_ih@[1,x] + b_ih + b_hh + W_hh@h0 ----
    {
        const float* wi0 = W_ih + (size_t)r0 * (IDIM + 1);
        const float* wi1 = wi0 + (IDIM + 1);
        float ai0 = 0.f, ai1 = 0.f;
        #pragma unroll 8
        for (int k = lane; k < IDIM; k += 32) {
            float xv = sh_x[k];
            ai0 += __ldg(wi0 + 1 + k) * xv;
            ai1 += __ldg(wi1 + 1 + k) * xv;
        }

        const float4* wh0 = (const float4*)(W_hh + (size_t)r0 * HDIM);
        const float4* wh1 = wh0 + (HDIM / 4);
        const float4* hv  = (const float4*)sh_h;
        float ah0 = 0.f, ah1 = 0.f;
        #pragma unroll 4
        for (int k = lane; k < HDIM / 4; k += 32) {
            float4 h4 = hv[k];
            float4 w0 = __ldg(wh0 + k);
            float4 w1 = __ldg(wh1 + k);
            ah0 += w0.x * h4.x + w0.y * h4.y + w0.z * h4.z + w0.w * h4.w;
            ah1 += w1.x * h4.x + w1.y * h4.y + w1.z * h4.z + w1.w * h4.w;
        }

        ai0 = warp_reduce(ai0); ai1 = warp_reduce(ai1);
        ah0 = warp_reduce(ah0); ah1 = warp_reduce(ah1);

        if (lane == 0) {
            float b0 = ai0 + b_ih[r0 + 0] + b_hh[r0 + 0];
            float b1 = ai1 + b_ih[r0 + 1] + b_hh[r0 + 1];
            g_gx_buf[r0 + 0] = b0;
            g_gx_buf[r0 + 1] = b1;
            g_gates[0][r0 + 0] = b0 + wi0[0] + ah0;   // flag column active at t=0
            g_gates[0][r0 + 1] = b1 + wi1[0] + ah1;
        }
    }
    grid_sync();

    // ---- adaptive loop: ONE grid barrier per step ----
    float cum = 0.0f;
    int   halted_t = MAX_STEPS - 1;
    int   buf = 0;

    for (int t = 0; t < MAX_STEPS; ++t) {
        // phase B: activations + halt (redundant per block, block-local state)
        const float* gt = g_gates[buf];
        float part = 0.0f;
        #pragma unroll
        for (int j = tid; j < HDIM; j += NTHREAD) {
            float gi = gt[j];
            float gf = gt[HDIM + j];
            float gg = gt[2 * HDIM + j];
            float go = gt[3 * HDIM + j];
            float cn = sigmoidf_(gf) * sh_c[j] + sigmoidf_(gi) * tanhf(gg);
            float hn = sigmoidf_(go) * tanhf(cn);
            sh_c[j] = cn;
            sh_h[j] = hn;
            part += w_halt[j] * hn;
        }
        part = warp_reduce(part);
        if (lane == 0) s_red[warp] = part;
        __syncthreads();
        float dot = 0.0f;
        #pragma unroll
        for (int w2 = 0; w2 < WPB; ++w2) dot += s_red[w2];
        float p = sigmoidf_(dot + bh);
        cum += p;
        if (cum >= 0.99f || t == MAX_STEPS - 1) { halted_t = t; break; }

        // phase A for step t+1: gates = gx + W_hh @ h (2 rows/warp)
        buf ^= 1;
        float* gn = g_gates[buf];
        {
            const float4* wh0 = (const float4*)(W_hh + (size_t)r0 * HDIM);
            const float4* wh1 = wh0 + (HDIM / 4);
            const float4* hv  = (const float4*)sh_h;
            float ah0 = 0.f, ah1 = 0.f;
            #pragma unroll 4
            for (int k = lane; k < HDIM / 4; k += 32) {
                float4 h4 = hv[k];
                float4 w0 = __ldg(wh0 + k);
                float4 w1 = __ldg(wh1 + k);
                ah0 += w0.x * h4.x + w0.y * h4.y + w0.z * h4.z + w0.w * h4.w;
                ah1 += w1.x * h4.x + w1.y * h4.y + w1.z * h4.z + w1.w * h4.w;
            }
            ah0 = warp_reduce(ah0);
            ah1 = warp_reduce(ah1);
            if (lane == 0) {
                gn[r0 + 0] = g_gx_buf[r0 + 0] + ah0;
                gn[r0 + 1] = g_gx_buf[r0 + 1] + ah1;
            }
        }
        grid_sync();
    }

    // ---- epilogue (barrier-free): out = W_out @ h + b_out ----
    // Each W_out row is split across 4 consecutive warps of one block
    // (quarter of k each); partials combined via shared memory.
    __syncthreads();
    {
        const int row = gwarp >> 2;          // 0..1023
        const int q   = gwarp & 3;           // k-quarter
        const float4* wr = (const float4*)(W_out + (size_t)row * HDIM) + q * (HDIM / 16);
        const float4* hv = (const float4*)sh_h + q * (HDIM / 16);
        float a = 0.f;
        #pragma unroll 4
        for (int k = lane; k < HDIM / 16; k += 32) {   // 128 float4s per quarter
            float4 w  = __ldg(wr + k);
            float4 h4 = hv[k];
            a += w.x * h4.x + w.y * h4.y + w.z * h4.z + w.w * h4.w;
        }
        a = warp_reduce(a);
        if (lane == 0) s_red[warp] = a;
        __syncthreads();
        if ((warp & 3) == 0 && lane == 0) {
            out[row] = s_red[warp] + s_red[warp + 1] + s_red[warp + 2]
                     + s_red[warp + 3] + b_out[row];
        }
    }

    if (blockIdx.x == 0) {
        for (int j = tid; j < HDIM; j += NTHREAD) {
            out[ODIM + j]        = sh_h[j];
            out[ODIM + HDIM + j] = sh_c[j];
        }
        if (tid == 0) out[ODIM + 2 * HDIM] = (float)halted_t;
    }
}

extern "C" void kernel_launch(void* const* d_in, const int* in_sizes, int n_in,
                              void* d_out, int out_size) {
    (void)in_sizes; (void)n_in; (void)out_size;
    const float* x      = (const float*)d_in[0];
    const float* h0     = (const float*)d_in[1];
    const float* c0     = (const float*)d_in[2];
    const float* W_ih   = (const float*)d_in[3];
    const float* W_hh   = (const float*)d_in[4];
    const float* b_ih   = (const float*)d_in[5];
    const float* b_hh   = (const float*)d_in[6];
    const float* w_halt = (const float*)d_in[7];
    const float* b_halt = (const float*)d_in[8];
    const float* W_out  = (const float*)d_in[9];
    const float* b_out  = (const float*)d_in[10];
    float* out = (float*)d_out;

    act_lstm_kernel<<<NBLOCK, NTHREAD>>>(x, h0, c0, W_ih, W_hh, b_ih, b_hh,
                                         w_halt, b_halt, W_out, b_out, out);
}